// round 6
// baseline (speedup 1.0000x reference)
#include <cuda_runtime.h>

// VectorQuantizer fused: z_e [32,64,32,32] f32, emb [1024,64] f32
// out (f32): z_st [2097152], loss, perplexity, encodings [32768 x 1024]

#define ND 64
#define NDP 32                       // d-pairs
#define NK 1024
#define HW 1024
#define NN 32768
#define ZELEMS 2097152
#define ROWS 64                      // rows per block
#define NBLK (NN / ROWS)             // 512
#define XST 66                       // xs row stride (floats), padded

typedef unsigned long long u64;

__device__ u64    g_embT[NDP * NK];  // [dp][k] = (e[k][2dp], e[k][2dp+1])
__device__ float  g_e2[NK];
__device__ int    g_counts[NK];
__device__ double g_losspart[NBLK];

static __device__ __forceinline__ void upk2(u64 v, float& lo, float& hi) {
    asm("mov.b64 {%0, %1}, %2;" : "=f"(lo), "=f"(hi) : "l"(v));
}
static __device__ __forceinline__ void fma2(u64& acc, u64 a, u64 b) {
    asm("fma.rn.f32x2 %0, %1, %2, %0;" : "+l"(acc) : "l"(a), "l"(b));
}
static __device__ __forceinline__ u64 umin64(u64 a, u64 b) { return a < b ? a : b; }

// ---------------------------------------------------------------------------
// prep: transposed d-pair emb table + e2 + counts. grid 256 x 128
// ---------------------------------------------------------------------------
__global__ void vq_prep(const float* __restrict__ emb) {
    const int t = blockIdx.x * 128 + threadIdx.x;     // 0..32767
    const int dp = t >> 10, k = t & (NK - 1);
    g_embT[t] = ((const u64*)emb)[k * NDP + dp];      // coalesced write

    if (t < NK) {
        g_counts[t] = 0;
        const float* er = emb + t * ND;
        double s0 = 0.0, s1 = 0.0, s2 = 0.0, s3 = 0.0;   // 4 chains: latency /4
#pragma unroll
        for (int i = 0; i < 16; i++) {
            double a = (double)er[4 * i],     b = (double)er[4 * i + 1];
            double c = (double)er[4 * i + 2], d = (double)er[4 * i + 3];
            s0 += a * a; s1 += b * b; s2 += c * c; s3 += d * d;
        }
        g_e2[t] = (float)(((s0 + s1) + s2) + s3);
    }
}

// ---------------------------------------------------------------------------
// fused main: argmin + z_st + loss + counts + encodings (zeros + ones)
// block = 64 rows x all 1024 codes; warp w -> rows 8w..8w+7; lane g ->
// codes {ct*128 + g + 32c}. acc packed f32x2 over d-pairs. grid 512 x 256.
// Register diet: a[] from smem per-ct, enc fill upfront, 2-half row split.
// ---------------------------------------------------------------------------
__global__ __launch_bounds__(256, 2) void vq_main(const float* __restrict__ ze,
                                                  float* __restrict__ out) {
    __shared__ float  xs[ROWS * XST];    // [row][d], padded (16.9 KB)
    __shared__ float  sa[ROWS];          // ||x||^2 per row
    __shared__ float  se2[NK];           // 4 KB
    __shared__ double red[256];

    const int tid  = threadIdx.x;
    const int w    = tid >> 5;
    const int g    = tid & 31;
    const int row0 = blockIdx.x * ROWS;
    const int b    = row0 >> 10;
    const int hw0  = row0 & (HW - 1);

    // stage x tile: xs[r][d] = ze[b][d][hw0+r]  (coalesced global reads)
    const float* zbase = ze + (size_t)b * ND * HW + hw0;
#pragma unroll
    for (int i = 0; i < 16; i++) {
        const int idx = tid + i * 256;
        const int d = idx >> 6, r = idx & 63;
        xs[r * XST + d] = zbase[(size_t)d * HW + r];
    }
#pragma unroll
    for (int i = 0; i < 4; i++) se2[tid + i * 256] = g_e2[tid + i * 256];
    __syncthreads();

    // ||x||^2: all 256 threads, row = tid&63, d-segment = tid>>6 (16 d each)
    {
        const int r = tid & 63, seg = tid >> 6;
        const float* xr = xs + r * XST + seg * 16;
        double s = 0.0;
#pragma unroll
        for (int i = 0; i < 16; i++) { double v = (double)xr[i]; s += v * v; }
        red[tid] = s;
    }
    __syncthreads();
    if (tid < ROWS)   // fixed combine order: deterministic
        sa[tid] = (float)(((red[tid] + red[tid + 64]) + red[tid + 128]) + red[tid + 192]);

    // encodings zero-fill upfront: stores drain on DRAM under the GEMM phase
    float* encrow = out + (size_t)ZELEMS + 2 + (size_t)row0 * NK;
    if (tid == 64) *(float2*)encrow = make_float2(0.0f, 0.0f);                   // head
    if (tid == 65) *(float2*)(encrow + ROWS * NK - 2) = make_float2(0.0f, 0.0f); // tail
    float4* enc4 = (float4*)(encrow + 2);            // 16383 aligned float4 slots
    {
        const float4 z4 = make_float4(0.0f, 0.0f, 0.0f, 0.0f);
#pragma unroll
        for (int j = 0; j < 64; j++) {
            const int s = j * 256 + tid;
            if (s < 16383) enc4[s] = z4;
        }
    }
    __syncthreads();   // sa ready; zero-fill ordered before later one-writes

    u64 bestk[8];
#pragma unroll
    for (int r = 0; r < 8; r++) bestk[r] = 0xFFFFFFFFFFFFFFFFULL;

    const float* xw = xs + (8 * w) * XST;

    for (int ct = 0; ct < 8; ct++) {
        const u64* __restrict__ bq = g_embT + ct * 128 + g;
        u64 acc[32];
#pragma unroll
        for (int i = 0; i < 32; i++) acc[i] = 0ULL;

#pragma unroll 2
        for (int dp = 0; dp < NDP; dp++) {
            u64 bv[4];
#pragma unroll
            for (int c = 0; c < 4; c++) bv[c] = bq[(size_t)dp * NK + 32 * c];  // coalesced, L1-resident
#pragma unroll
            for (int rh = 0; rh < 2; rh++) {        // 2 halves: only 4 av live
#pragma unroll
                for (int r4 = 0; r4 < 4; r4++) {
                    const int r = rh * 4 + r4;
                    const u64 av = *(const u64*)(xw + r * XST + 2 * dp);  // broadcast LDS.64
#pragma unroll
                    for (int c = 0; c < 4; c++) fma2(acc[r * 4 + c], av, bv[c]);
                }
            }
        }

        // dist = fl(fl(a+e2) - 2*dot); key keeps lowest-index ties
#pragma unroll
        for (int c = 0; c < 4; c++) {
            const int code = ct * 128 + g + 32 * c;
            const float e2 = se2[code];
#pragma unroll
            for (int r = 0; r < 8; r++) {
                float lo, hi;
                upk2(acc[r * 4 + c], lo, hi);
                const float dist = fmaf(-2.0f, lo + hi, sa[8 * w + r] + e2);
                const u64 key = ((u64)__float_as_uint(dist) << 32) | (unsigned)code;
                bestk[r] = umin64(bestk[r], key);
            }
        }
    }

    // warp reduce over lanes (each lane saw a disjoint code subset)
#pragma unroll
    for (int off = 16; off > 0; off >>= 1)
#pragma unroll
        for (int r = 0; r < 8; r++)
            bestk[r] = umin64(bestk[r], __shfl_down_sync(0xFFFFFFFFu, bestk[r], off));
    int codes[8];
#pragma unroll
    for (int r = 0; r < 8; r++)
        codes[r] = (int)(__shfl_sync(0xFFFFFFFFu, bestk[r], 0) & 0xFFFFFFFFULL);

    // one-hot ones + counts (zero-fill ordered by the pre-loop barrier)
    if (g < 8) {
        const int row = 8 * w + g;
        const int cd  = codes[g];
        encrow[(size_t)row * NK + cd] = 1.0f;
        atomicAdd(&g_counts[cd], 1);
    }

    // z_st + loss: 4 lanes per row, each covers 8 d-pairs
    const int r   = g >> 2;
    const int row = 8 * w + r;
    const int cd  = codes[r];
    const int dpg = g & 3;
    float* op = out + (size_t)b * ND * HW + hw0 + row;
    double ls = 0.0;
#pragma unroll
    for (int i = 0; i < 8; i++) {
        const int dp = dpg * 8 + i;
        float x0, x1, e0, e1;
        upk2(*(const u64*)(xs + row * XST + 2 * dp), x0, x1);
        upk2(g_embT[dp * NK + cd], e0, e1);
        const float d0 = e0 - x0, d1 = e1 - x1;
        op[(size_t)(2 * dp) * HW]     = x0 + d0;     // z + (z_q - z)
        op[(size_t)(2 * dp + 1) * HW] = x1 + d1;
        ls += (double)(d0 * d0) + (double)(d1 * d1);
    }
    __syncthreads();   // red free for reuse
    red[tid] = ls;
    __syncthreads();
    for (int st = 128; st > 0; st >>= 1) {
        if (tid < st) red[tid] += red[tid + st];
        __syncthreads();
    }
    if (tid == 0) g_losspart[blockIdx.x] = red[0];
}

// ---------------------------------------------------------------------------
// finalize: loss + perplexity. 1 x 256
// ---------------------------------------------------------------------------
__global__ void vq_fin(float* __restrict__ out) {
    __shared__ double se[256];
    __shared__ double sl[256];
    const int t = threadIdx.x;
    double ent = 0.0;
#pragma unroll
    for (int i = 0; i < 4; i++) {
        const int k = t + 256 * i;
        const float p = (float)g_counts[k] / (float)NN;
        ent += (double)(p * logf(p + 1e-10f));
    }
    se[t] = ent;
    sl[t] = g_losspart[t] + g_losspart[t + 256];
    __syncthreads();
    for (int st = 128; st > 0; st >>= 1) {
        if (t < st) { se[t] += se[t + st]; sl[t] += sl[t + st]; }
        __syncthreads();
    }
    if (t == 0) {
        const float m = (float)(sl[0] / (double)ZELEMS);  // q_latent == e_latent
        out[ZELEMS]     = m + 0.25f * m;
        out[ZELEMS + 1] = expf(-(float)se[0]);
    }
}

extern "C" void kernel_launch(void* const* d_in, const int* in_sizes, int n_in,
                              void* d_out, int out_size) {
    const float* ze  = (const float*)d_in[0];
    const float* emb = (const float*)d_in[1];
    float*       out = (float*)d_out;

    vq_prep<<<256, 128>>>(emb);
    vq_main<<<NBLK, 256>>>(ze, out);
    vq_fin<<<1, 256>>>(out);
}